// round 15
// baseline (speedup 1.0000x reference)
#include <cuda_runtime.h>
#include <cuda_bf16.h>
#include <cuda_fp16.h>
#include <stdint.h>

#define BSZ   8
#define TLEN  4096
#define EDIM  1024
#define HDIM  128
#define MTOT  (BSZ * TLEN)

// Q,K: bf16 hi/lo row-major [t][h]. V: single fp16 row-major.
__device__ __nv_bfloat16 Qhi_g[MTOT * HDIM], Qlo_g[MTOT * HDIM];
__device__ __nv_bfloat16 Khi_g[MTOT * HDIM], Klo_g[MTOT * HDIM];
__device__ __half V16_g[MTOT * HDIM];
// pre-split weights [which][k][n]
__device__ __nv_bfloat16 Whi_g[3 * EDIM * HDIM], Wlo_g[3 * EDIM * HDIM];

// ---------------- helpers ----------------
__device__ __forceinline__ uint32_t smem_to_u32(const void* p) {
    uint32_t a;
    asm("{ .reg .u64 t; cvta.to.shared.u64 t, %1; cvt.u32.u64 %0, t; }" : "=r"(a) : "l"(p));
    return a;
}
#define LDSM4(R, A) asm volatile( \
    "ldmatrix.sync.aligned.m8n8.x4.shared.b16 {%0,%1,%2,%3}, [%4];" \
    : "=r"((R)[0]), "=r"((R)[1]), "=r"((R)[2]), "=r"((R)[3]) : "r"(A))
#define LDSM4T(R, A) asm volatile( \
    "ldmatrix.sync.aligned.m8n8.x4.trans.shared.b16 {%0,%1,%2,%3}, [%4];" \
    : "=r"((R)[0]), "=r"((R)[1]), "=r"((R)[2]), "=r"((R)[3]) : "r"(A))
#define MMA(C, A, B) asm volatile( \
    "mma.sync.aligned.m16n8k16.row.col.f32.bf16.bf16.f32 " \
    "{%0,%1,%2,%3},{%4,%5,%6,%7},{%8,%9},{%0,%1,%2,%3};" \
    : "+f"((C)[0]), "+f"((C)[1]), "+f"((C)[2]), "+f"((C)[3]) \
    : "r"((A)[0]), "r"((A)[1]), "r"((A)[2]), "r"((A)[3]), "r"((B)[0]), "r"((B)[1]))
#define MMAH(C, A, B) asm volatile( \
    "mma.sync.aligned.m16n8k16.row.col.f32.f16.f16.f32 " \
    "{%0,%1,%2,%3},{%4,%5,%6,%7},{%8,%9},{%0,%1,%2,%3};" \
    : "+f"((C)[0]), "+f"((C)[1]), "+f"((C)[2]), "+f"((C)[3]) \
    : "r"((A)[0]), "r"((A)[1]), "r"((A)[2]), "r"((A)[3]), "r"((B)[0]), "r"((B)[1]))
#define CPA(S, G) asm volatile("cp.async.cg.shared.global [%0], [%1], 16;" \
    :: "r"(S), "l"(G))
#define CPC() asm volatile("cp.async.commit_group;")

__device__ __forceinline__ float fexp(float x) {      // FMA-pipe exp, ~2e-6 rel
    float t = x * 1.4426950408889634f;
    float k = rintf(t);
    float u = (t - k) * 0.6931471805599453f;
    float p = 1.f + u * (1.f + u * (0.5f + u * (0.16666667f +
              u * (0.041666667f + u * 0.0083333333f))));
    return p * __int_as_float(((int)k + 127) << 23);
}
__device__ __forceinline__ uint32_t b2u(__nv_bfloat16 a, __nv_bfloat16 b) {
    __nv_bfloat162 t; t.x = a; t.y = b; return *(uint32_t*)&t;
}
__device__ __forceinline__ uint32_t h2u(float a, float b) {
    __half2 t = __floats2half2_rn(a, b);
    return *(uint32_t*)&t;
}
__device__ __forceinline__ void splitf(float f, __nv_bfloat16& h, __nv_bfloat16& l) {
    h = __float2bfloat16(f);
    l = __float2bfloat16(f - __bfloat162float(h));
}

// ---------------------------------------------------------------------------
// Kernel 0: split W into bf16 hi/lo.
// ---------------------------------------------------------------------------
__global__ __launch_bounds__(512) void split_w(const float* __restrict__ Wq,
                                               const float* __restrict__ Wk,
                                               const float* __restrict__ Wv) {
    int t = blockIdx.x * 512 + threadIdx.x;
    int base = t * 8;
    int which = base >> 17;
    const float* s = ((which == 0) ? Wq : (which == 1) ? Wk : Wv) + (base & 131071);
    float4 a = *(const float4*)s, b = *(const float4*)(s + 4);
    float f[8] = {a.x, a.y, a.z, a.w, b.x, b.y, b.z, b.w};
    uint32_t hp[4], lp[4];
#pragma unroll
    for (int i = 0; i < 4; i++) {
        __nv_bfloat16 h0, l0, h1, l1;
        splitf(f[2 * i], h0, l0);
        splitf(f[2 * i + 1], h1, l1);
        hp[i] = b2u(h0, h1);
        lp[i] = b2u(l0, l1);
    }
    *(uint4*)(Whi_g + base) = make_uint4(hp[0], hp[1], hp[2], hp[3]);
    *(uint4*)(Wlo_g + base) = make_uint4(lp[0], lp[1], lp[2], lp[3]);
}

// ---------------------------------------------------------------------------
// Kernel 1: projection, flash-style tiling: BM=64, 128 threads, 3 CTAs/SM.
// grid (512, 3): which = 0 Q (scaled), 1 K, 2 V(fp16).
// smem/CTA: A hi/lo (64x144B) + B hi/lo (64x272B) = 53248 B.
// ---------------------------------------------------------------------------
#define PA_STR 144
#define PB_STR 272
#define PA_TILE (64 * PA_STR)            // 9216
#define PB_TILE (64 * PB_STR)            // 17408
#define PSM_TOT (2 * PA_TILE + 2 * PB_TILE)   // 53248

__global__ __launch_bounds__(128, 3) void proj_mma(const float* __restrict__ X) {
    extern __shared__ char psm[];
    const int which = blockIdx.y;
    const int m0 = blockIdx.x * 64, tid = threadIdx.x;
    const int w = tid >> 5, l = tid & 31;
    const int sub = l >> 3, l7 = l & 7;
    const uint32_t smb = smem_to_u32(psm);
    const uint32_t A_hi = smb, A_lo = smb + PA_TILE;
    const uint32_t B_hi = smb + 2 * PA_TILE, B_lo = B_hi + PB_TILE;

    const uint32_t aoff = (uint32_t)(w * 16 + l7 + (sub & 1) * 8) * PA_STR + (l >> 4) * 16;
    const uint32_t boff = (uint32_t)((sub & 1) * 8 + l7) * PB_STR + (l >> 4) * 16;

    const __nv_bfloat16* wh = Whi_g + which * 131072;
    const __nv_bfloat16* wl = Wlo_g + which * 131072;

    float acc[16][4];
#pragma unroll
    for (int i = 0; i < 16; i++) acc[i][0] = acc[i][1] = acc[i][2] = acc[i][3] = 0.f;
    float4 xa[8];   // full 64x64 A tile: 8 iters x 128 threads = 1024 float4

    // prologue: x regs for step 0 + B(0) cp.async
#pragma unroll
    for (int i = 0; i < 8; i++) {
        int idx = tid + i * 128, r = idx >> 4, c4 = idx & 15;
        xa[i] = *(const float4*)(X + (size_t)(m0 + r) * EDIM + c4 * 4);
    }
#pragma unroll
    for (int i = 0; i < 8; i++) {
        int u = tid + i * 128, r = u >> 4, c = u & 15;
        CPA(B_hi + r * PB_STR + c * 16, wh + r * HDIM + c * 8);
        CPA(B_lo + r * PB_STR + c * 16, wl + r * HDIM + c * 8);
    }
    CPC();

    for (int s = 0; s < 16; s++) {
        // split-store A(s) (A buffer free: post-MMA sync of step s-1)
#pragma unroll
        for (int i = 0; i < 8; i++) {
            int idx = tid + i * 128, r = idx >> 4, c4 = idx & 15;
            __nv_bfloat16 h0, l0, h1, l1, h2, l2, h3, l3;
            splitf(xa[i].x, h0, l0); splitf(xa[i].y, h1, l1);
            splitf(xa[i].z, h2, l2); splitf(xa[i].w, h3, l3);
            uint32_t o = r * PA_STR + c4 * 8;
            *(uint2*)(psm + o)           = make_uint2(b2u(h0, h1), b2u(h2, h3));
            *(uint2*)(psm + PA_TILE + o) = make_uint2(b2u(l0, l1), b2u(l2, l3));
        }
        asm volatile("cp.async.wait_group 0;");
        __syncthreads();

        // prefetch next x tile into regs (overlaps MMA)
        if (s < 15) {
            int k0n = (s + 1) * 64;
#pragma unroll
            for (int i = 0; i < 8; i++) {
                int idx = tid + i * 128, r = idx >> 4, c4 = idx & 15;
                xa[i] = *(const float4*)(X + (size_t)(m0 + r) * EDIM + k0n + c4 * 4);
            }
        }

#pragma unroll
        for (int kc = 0; kc < 4; kc++) {
            uint32_t ah[4], al[4];
            LDSM4(ah, A_hi + aoff + kc * 32);
            LDSM4(al, A_lo + aoff + kc * 32);
#pragma unroll
            for (int ng = 0; ng < 8; ng++) {
                uint32_t bh[4], bl[4];
                uint32_t ba = B_hi + boff + kc * (16 * PB_STR) + ng * 32;
                LDSM4T(bh, ba);
                LDSM4T(bl, ba + PB_TILE);
                MMA(acc[2 * ng], ah, bh);     MMA(acc[2 * ng], ah, bl);
                MMA(acc[2 * ng], al, bh);
                MMA(acc[2 * ng + 1], ah, bh + 2); MMA(acc[2 * ng + 1], ah, bl + 2);
                MMA(acc[2 * ng + 1], al, bh + 2);
            }
        }
        __syncthreads();

        // issue next B tile (single buffer: safe after sync)
        if (s < 15) {
            const __nv_bfloat16* whn = wh + (size_t)(s + 1) * 64 * HDIM;
            const __nv_bfloat16* wln = wl + (size_t)(s + 1) * 64 * HDIM;
#pragma unroll
            for (int i = 0; i < 8; i++) {
                int u = tid + i * 128, r = u >> 4, c = u & 15;
                CPA(B_hi + r * PB_STR + c * 16, whn + r * HDIM + c * 8);
                CPA(B_lo + r * PB_STR + c * 16, wln + r * HDIM + c * 8);
            }
            CPC();
        }
    }

    const int gl = l >> 2, tq = l & 3;
    const size_t r0 = (size_t)m0 + w * 16 + gl;
    if (which == 2) {
#pragma unroll
        for (int t = 0; t < 16; t++) {
            int col = t * 8 + tq * 2;
            *(uint32_t*)(V16_g + r0 * HDIM + col)       = h2u(acc[t][0], acc[t][1]);
            *(uint32_t*)(V16_g + (r0 + 8) * HDIM + col) = h2u(acc[t][2], acc[t][3]);
        }
    } else {
        const float sc = (which == 0) ? 0.08838834764831845f : 1.f;
        __nv_bfloat16* dh = (which == 0) ? Qhi_g : Khi_g;
        __nv_bfloat16* dl = (which == 0) ? Qlo_g : Klo_g;
#pragma unroll
        for (int t = 0; t < 16; t++) {
            int col = t * 8 + tq * 2;
            __nv_bfloat16 h0, l0, h1, l1;
            splitf(acc[t][0] * sc, h0, l0); splitf(acc[t][1] * sc, h1, l1);
            *(uint32_t*)(dh + r0 * HDIM + col) = b2u(h0, h1);
            *(uint32_t*)(dl + r0 * HDIM + col) = b2u(l0, l1);
            splitf(acc[t][2] * sc, h0, l0); splitf(acc[t][3] * sc, h1, l1);
            *(uint32_t*)(dh + (r0 + 8) * HDIM + col) = b2u(h0, h1);
            *(uint32_t*)(dl + (r0 + 8) * HDIM + col) = b2u(l0, l1);
        }
    }
}

// ---------------------------------------------------------------------------
// Kernel 2: flash, BQ=64, 128 threads, 2 CTAs/SM. Q in registers. (R12 win.)
// ---------------------------------------------------------------------------
#define F_STR  272
#define F_TILE 17408u
#define SM_Q   0u
#define SM_K   (2u * F_TILE)
#define SM_V   (4u * F_TILE)
#define F_SM_TOT (5 * F_TILE)    // 87040

__device__ __forceinline__ void k_issue(uint32_t smb, int b, int t0, int tid) {
#pragma unroll
    for (int t = 0; t < 2; t++) {
        const __nv_bfloat16* src = (t ? Klo_g : Khi_g) + ((size_t)b * TLEN + t0) * HDIM;
#pragma unroll
        for (int i = 0; i < 8; i++) {
            int u = tid + i * 128, r = u >> 4, c = u & 15;
            CPA(smb + SM_K + t * F_TILE + r * F_STR + c * 16, src + r * HDIM + c * 8);
        }
    }
    CPC();
}
__device__ __forceinline__ void v_issue(uint32_t smb, int b, int t0, int tid) {
    const __half* src = V16_g + ((size_t)b * TLEN + t0) * HDIM;
#pragma unroll
    for (int i = 0; i < 8; i++) {
        int u = tid + i * 128, r = u >> 4, c = u & 15;
        CPA(smb + SM_V + r * F_STR + c * 16, src + r * HDIM + c * 8);
    }
    CPC();
}

__global__ void __launch_bounds__(128, 2) flash_mma(float* __restrict__ Out) {
    extern __shared__ char sm[];
    const uint32_t smb = smem_to_u32(sm);
    const int tid = threadIdx.x, w = tid >> 5, l = tid & 31;
    const int qt = 63 - (int)blockIdx.y, b = blockIdx.x;
    const size_t gq0 = (size_t)b * TLEN + (size_t)qt * 64;
    const int nsteps = qt + 1;

    // prologue: Q tiles (group 1) + K(0) (group 2)
#pragma unroll
    for (int t = 0; t < 2; t++) {
        const __nv_bfloat16* src = (t ? Qlo_g : Qhi_g) + gq0 * HDIM;
#pragma unroll
        for (int i = 0; i < 8; i++) {
            int u = tid + i * 128, r = u >> 4, c = u & 15;
            CPA(smb + SM_Q + t * F_TILE + r * F_STR + c * 16, src + r * HDIM + c * 8);
        }
    }
    CPC();
    k_issue(smb, b, 0, tid);

    const int sub = l >> 3, l7 = l & 7;
    const uint32_t qoffb = smb + SM_Q + (uint32_t)(w * 16 + l7 + (sub & 1) * 8) * F_STR + (l >> 4) * 16;
    const uint32_t koff  = smb + SM_K + (uint32_t)((sub >> 1) * 8 + l7) * F_STR + (sub & 1) * 16;
    const uint32_t voff  = smb + SM_V + (uint32_t)((sub & 1) * 8 + l7) * F_STR + (l >> 4) * 16;
    const int gl = l >> 2, tq = l & 3;
    const int rg0 = qt * 64 + w * 16 + gl;

    asm volatile("cp.async.wait_group 1;");
    __syncthreads();
    uint32_t qh_r[8][4], ql_r[8][4];
#pragma unroll
    for (int kc = 0; kc < 8; kc++) {
        LDSM4(qh_r[kc], qoffb + kc * 32);
        LDSM4(ql_r[kc], qoffb + F_TILE + kc * 32);
    }

    float o[16][4];
#pragma unroll
    for (int i = 0; i < 16; i++) o[i][0] = o[i][1] = o[i][2] = o[i][3] = 0.f;
    float la0 = 0.f, la1 = 0.f;

    for (int kt = 0; kt < nsteps; kt++) {
        const int t0 = kt * 64;
        asm volatile("cp.async.wait_group 0;");   // K(kt) arrived
        __syncthreads();                           // V buffer free, K visible
        v_issue(smb, b, t0, tid);                  // V(kt) arrives during S

        float s[8][4];
#pragma unroll
        for (int i = 0; i < 8; i++) s[i][0] = s[i][1] = s[i][2] = s[i][3] = 0.f;
#pragma unroll
        for (int kc = 0; kc < 8; kc++) {
            uint32_t kh[4][4], kl[4][4];
#pragma unroll
            for (int g = 0; g < 4; g++) {
                uint32_t ka = koff + g * (16 * F_STR) + kc * 32;
                LDSM4(kh[g], ka);
                LDSM4(kl[g], ka + F_TILE);
            }
#pragma unroll
            for (int g = 0; g < 4; g++) {
                MMA(s[2 * g], qh_r[kc], kh[g]);
                MMA(s[2 * g + 1], qh_r[kc], kh[g] + 2);
            }
#pragma unroll
            for (int g = 0; g < 4; g++) {
                MMA(s[2 * g], qh_r[kc], kl[g]);
                MMA(s[2 * g + 1], qh_r[kc], kl[g] + 2);
            }
#pragma unroll
            for (int g = 0; g < 4; g++) {
                MMA(s[2 * g], ql_r[kc], kh[g]);
                MMA(s[2 * g + 1], ql_r[kc], kh[g] + 2);
            }
        }

        asm volatile("cp.async.wait_group 0;");   // V(kt) arrived
        __syncthreads();                           // S K-reads done + V visible
        if (kt + 1 < nsteps)
            k_issue(smb, b, t0 + 64, tid);         // K(kt+1) arrives during PV

        const bool msk = (kt == qt);
#pragma unroll
        for (int kc2 = 0; kc2 < 4; kc2++) {
            uint32_t pc[4];
#pragma unroll
            for (int h = 0; h < 2; h++) {
                const int nt = 2 * kc2 + h;
                int col = t0 + nt * 8 + tq * 2;
                float e0 = fexp(s[nt][0]), e1 = fexp(s[nt][1]);
                float e2 = fexp(s[nt][2]), e3 = fexp(s[nt][3]);
                if (msk) {
                    if (col > rg0) e0 = 0.f;
                    if (col + 1 > rg0) e1 = 0.f;
                    if (col > rg0 + 8) e2 = 0.f;
                    if (col + 1 > rg0 + 8) e3 = 0.f;
                }
                la0 += e0 + e1;
                la1 += e2 + e3;
                pc[h * 2 + 0] = h2u(e0, e1);
                pc[h * 2 + 1] = h2u(e2, e3);
            }
#pragma unroll
            for (int ng = 0; ng < 2; ng++) {
                uint32_t vf[4][4];
#pragma unroll
                for (int j = 0; j < 4; j++) {
                    uint32_t va = voff + kc2 * (16 * F_STR) + (ng * 4 + j) * 32;
                    LDSM4T(vf[j], va);
                }
#pragma unroll
                for (int j = 0; j < 4; j++) {
                    MMAH(o[2 * (ng * 4 + j)], pc, vf[j]);
                    MMAH(o[2 * (ng * 4 + j) + 1], pc, vf[j] + 2);
                }
            }
        }
    }

    la0 += __shfl_xor_sync(0xffffffffu, la0, 1);
    la0 += __shfl_xor_sync(0xffffffffu, la0, 2);
    la1 += __shfl_xor_sync(0xffffffffu, la1, 1);
    la1 += __shfl_xor_sync(0xffffffffu, la1, 2);
    const float rl0 = 1.f / la0, rl1 = 1.f / la1;
    float* o0 = Out + (gq0 + w * 16 + gl) * HDIM + tq * 2;
    float* o1 = o0 + 8 * HDIM;
#pragma unroll
    for (int nt2 = 0; nt2 < 16; nt2++) {
        *(float2*)(o0 + nt2 * 8) = make_float2(o[nt2][0] * rl0, o[nt2][1] * rl0);
        *(float2*)(o1 + nt2 * 8) = make_float2(o[nt2][2] * rl1, o[nt2][3] * rl1);
    }
}

// ---------------------------------------------------------------------------
extern "C" void kernel_launch(void* const* d_in, const int* in_sizes, int n_in,
                              void* d_out, int out_size) {
    const float* x  = (const float*)d_in[0];
    const float* Wq = (const float*)d_in[1];
    const float* Wk = (const float*)d_in[2];
    const float* Wv = (const float*)d_in[3];
    float* out = (float*)d_out;
    (void)in_sizes; (void)n_in; (void)out_size;

    split_w<<<96, 512>>>(Wq, Wk, Wv);

    cudaFuncSetAttribute(proj_mma, cudaFuncAttributeMaxDynamicSharedMemorySize, PSM_TOT);
    proj_mma<<<dim3(512, 3), 128, PSM_TOT>>>(x);

    cudaFuncSetAttribute(flash_mma, cudaFuncAttributeMaxDynamicSharedMemorySize, F_SM_TOT);
    flash_mma<<<dim3(BSZ, 64), 128, F_SM_TOT>>>(out);
}

// round 16
// speedup vs baseline: 1.1223x; 1.1223x over previous
#include <cuda_runtime.h>
#include <cuda_bf16.h>
#include <cuda_fp16.h>
#include <stdint.h>

#define BSZ   8
#define TLEN  4096
#define EDIM  1024
#define HDIM  128
#define MTOT  (BSZ * TLEN)

// Q,K,V: single fp16 row-major [t][h] (Q pre-scaled by 1/sqrt(H)).
__device__ __half Q16_g[MTOT * HDIM];
__device__ __half K16_g[MTOT * HDIM];
__device__ __half V16_g[MTOT * HDIM];
// pre-split weights [which][k][n] (proj stays bf16 3-split for accuracy)
__device__ __nv_bfloat16 Whi_g[3 * EDIM * HDIM], Wlo_g[3 * EDIM * HDIM];

// ---------------- helpers ----------------
__device__ __forceinline__ uint32_t smem_to_u32(const void* p) {
    uint32_t a;
    asm("{ .reg .u64 t; cvta.to.shared.u64 t, %1; cvt.u32.u64 %0, t; }" : "=r"(a) : "l"(p));
    return a;
}
#define LDSM4(R, A) asm volatile( \
    "ldmatrix.sync.aligned.m8n8.x4.shared.b16 {%0,%1,%2,%3}, [%4];" \
    : "=r"((R)[0]), "=r"((R)[1]), "=r"((R)[2]), "=r"((R)[3]) : "r"(A))
#define LDSM4T(R, A) asm volatile( \
    "ldmatrix.sync.aligned.m8n8.x4.trans.shared.b16 {%0,%1,%2,%3}, [%4];" \
    : "=r"((R)[0]), "=r"((R)[1]), "=r"((R)[2]), "=r"((R)[3]) : "r"(A))
#define MMA(C, A, B) asm volatile( \
    "mma.sync.aligned.m16n8k16.row.col.f32.bf16.bf16.f32 " \
    "{%0,%1,%2,%3},{%4,%5,%6,%7},{%8,%9},{%0,%1,%2,%3};" \
    : "+f"((C)[0]), "+f"((C)[1]), "+f"((C)[2]), "+f"((C)[3]) \
    : "r"((A)[0]), "r"((A)[1]), "r"((A)[2]), "r"((A)[3]), "r"((B)[0]), "r"((B)[1]))
#define MMAH(C, A, B) asm volatile( \
    "mma.sync.aligned.m16n8k16.row.col.f32.f16.f16.f32 " \
    "{%0,%1,%2,%3},{%4,%5,%6,%7},{%8,%9},{%0,%1,%2,%3};" \
    : "+f"((C)[0]), "+f"((C)[1]), "+f"((C)[2]), "+f"((C)[3]) \
    : "r"((A)[0]), "r"((A)[1]), "r"((A)[2]), "r"((A)[3]), "r"((B)[0]), "r"((B)[1]))
#define CPA(S, G) asm volatile("cp.async.cg.shared.global [%0], [%1], 16;" \
    :: "r"(S), "l"(G))
#define CPC() asm volatile("cp.async.commit_group;")

__device__ __forceinline__ float fexp(float x) {      // FMA-pipe exp, ~2e-6 rel
    float t = x * 1.4426950408889634f;
    float k = rintf(t);
    float u = (t - k) * 0.6931471805599453f;
    float p = 1.f + u * (1.f + u * (0.5f + u * (0.16666667f +
              u * (0.041666667f + u * 0.0083333333f))));
    return p * __int_as_float(((int)k + 127) << 23);
}
__device__ __forceinline__ uint32_t b2u(__nv_bfloat16 a, __nv_bfloat16 b) {
    __nv_bfloat162 t; t.x = a; t.y = b; return *(uint32_t*)&t;
}
__device__ __forceinline__ uint32_t h2u(float a, float b) {
    __half2 t = __floats2half2_rn(a, b);
    return *(uint32_t*)&t;
}
__device__ __forceinline__ void splitf(float f, __nv_bfloat16& h, __nv_bfloat16& l) {
    h = __float2bfloat16(f);
    l = __float2bfloat16(f - __bfloat162float(h));
}

// ---------------------------------------------------------------------------
// Kernel 0: split W into bf16 hi/lo.
// ---------------------------------------------------------------------------
__global__ __launch_bounds__(512) void split_w(const float* __restrict__ Wq,
                                               const float* __restrict__ Wk,
                                               const float* __restrict__ Wv) {
    int t = blockIdx.x * 512 + threadIdx.x;
    int base = t * 8;
    int which = base >> 17;
    const float* s = ((which == 0) ? Wq : (which == 1) ? Wk : Wv) + (base & 131071);
    float4 a = *(const float4*)s, b = *(const float4*)(s + 4);
    float f[8] = {a.x, a.y, a.z, a.w, b.x, b.y, b.z, b.w};
    uint32_t hp[4], lp[4];
#pragma unroll
    for (int i = 0; i < 4; i++) {
        __nv_bfloat16 h0, l0, h1, l1;
        splitf(f[2 * i], h0, l0);
        splitf(f[2 * i + 1], h1, l1);
        hp[i] = b2u(h0, h1);
        lp[i] = b2u(l0, l1);
    }
    *(uint4*)(Whi_g + base) = make_uint4(hp[0], hp[1], hp[2], hp[3]);
    *(uint4*)(Wlo_g + base) = make_uint4(lp[0], lp[1], lp[2], lp[3]);
}

// ---------------------------------------------------------------------------
// Kernel 1: projection, BM=64, 128 threads, 3 CTAs/SM. Output: single fp16.
// grid (512, 3): which = 0 Q (scaled), 1 K, 2 V.
// ---------------------------------------------------------------------------
#define PA_STR 144
#define PB_STR 272
#define PA_TILE (64 * PA_STR)            // 9216
#define PB_TILE (64 * PB_STR)            // 17408
#define PSM_TOT (2 * PA_TILE + 2 * PB_TILE)   // 53248

__global__ __launch_bounds__(128, 3) void proj_mma(const float* __restrict__ X) {
    extern __shared__ char psm[];
    const int which = blockIdx.y;
    const int m0 = blockIdx.x * 64, tid = threadIdx.x;
    const int w = tid >> 5, l = tid & 31;
    const int sub = l >> 3, l7 = l & 7;
    const uint32_t smb = smem_to_u32(psm);
    const uint32_t A_hi = smb, A_lo = smb + PA_TILE;
    const uint32_t B_hi = smb + 2 * PA_TILE, B_lo = B_hi + PB_TILE;

    const uint32_t aoff = (uint32_t)(w * 16 + l7 + (sub & 1) * 8) * PA_STR + (l >> 4) * 16;
    const uint32_t boff = (uint32_t)((sub & 1) * 8 + l7) * PB_STR + (l >> 4) * 16;

    const __nv_bfloat16* wh = Whi_g + which * 131072;
    const __nv_bfloat16* wl = Wlo_g + which * 131072;

    float acc[16][4];
#pragma unroll
    for (int i = 0; i < 16; i++) acc[i][0] = acc[i][1] = acc[i][2] = acc[i][3] = 0.f;
    float4 xa[8];   // full 64x64 A tile: 8 iters x 128 threads

    // prologue: x regs for step 0 + B(0) cp.async
#pragma unroll
    for (int i = 0; i < 8; i++) {
        int idx = tid + i * 128, r = idx >> 4, c4 = idx & 15;
        xa[i] = *(const float4*)(X + (size_t)(m0 + r) * EDIM + c4 * 4);
    }
#pragma unroll
    for (int i = 0; i < 8; i++) {
        int u = tid + i * 128, r = u >> 4, c = u & 15;
        CPA(B_hi + r * PB_STR + c * 16, wh + r * HDIM + c * 8);
        CPA(B_lo + r * PB_STR + c * 16, wl + r * HDIM + c * 8);
    }
    CPC();

    for (int s = 0; s < 16; s++) {
#pragma unroll
        for (int i = 0; i < 8; i++) {
            int idx = tid + i * 128, r = idx >> 4, c4 = idx & 15;
            __nv_bfloat16 h0, l0, h1, l1, h2, l2, h3, l3;
            splitf(xa[i].x, h0, l0); splitf(xa[i].y, h1, l1);
            splitf(xa[i].z, h2, l2); splitf(xa[i].w, h3, l3);
            uint32_t o = r * PA_STR + c4 * 8;
            *(uint2*)(psm + o)           = make_uint2(b2u(h0, h1), b2u(h2, h3));
            *(uint2*)(psm + PA_TILE + o) = make_uint2(b2u(l0, l1), b2u(l2, l3));
        }
        asm volatile("cp.async.wait_group 0;");
        __syncthreads();

        if (s < 15) {
            int k0n = (s + 1) * 64;
#pragma unroll
            for (int i = 0; i < 8; i++) {
                int idx = tid + i * 128, r = idx >> 4, c4 = idx & 15;
                xa[i] = *(const float4*)(X + (size_t)(m0 + r) * EDIM + k0n + c4 * 4);
            }
        }

#pragma unroll
        for (int kc = 0; kc < 4; kc++) {
            uint32_t ah[4], al[4];
            LDSM4(ah, A_hi + aoff + kc * 32);
            LDSM4(al, A_lo + aoff + kc * 32);
#pragma unroll
            for (int ng = 0; ng < 8; ng++) {
                uint32_t bh[4], bl[4];
                uint32_t ba = B_hi + boff + kc * (16 * PB_STR) + ng * 32;
                LDSM4T(bh, ba);
                LDSM4T(bl, ba + PB_TILE);
                MMA(acc[2 * ng], ah, bh);     MMA(acc[2 * ng], ah, bl);
                MMA(acc[2 * ng], al, bh);
                MMA(acc[2 * ng + 1], ah, bh + 2); MMA(acc[2 * ng + 1], ah, bl + 2);
                MMA(acc[2 * ng + 1], al, bh + 2);
            }
        }
        __syncthreads();

        if (s < 15) {
            const __nv_bfloat16* whn = wh + (size_t)(s + 1) * 64 * HDIM;
            const __nv_bfloat16* wln = wl + (size_t)(s + 1) * 64 * HDIM;
#pragma unroll
            for (int i = 0; i < 8; i++) {
                int u = tid + i * 128, r = u >> 4, c = u & 15;
                CPA(B_hi + r * PB_STR + c * 16, whn + r * HDIM + c * 8);
                CPA(B_lo + r * PB_STR + c * 16, wln + r * HDIM + c * 8);
            }
            CPC();
        }
    }

    // epilogue: single fp16 store (Q scaled by 1/sqrt(H))
    const float sc = (which == 0) ? 0.08838834764831845f : 1.f;
    __half* dst = (which == 0) ? Q16_g : (which == 1) ? K16_g : V16_g;
    const int gl = l >> 2, tq = l & 3;
    const size_t r0 = (size_t)m0 + w * 16 + gl;
#pragma unroll
    for (int t = 0; t < 16; t++) {
        int col = t * 8 + tq * 2;
        *(uint32_t*)(dst + r0 * HDIM + col)       = h2u(acc[t][0] * sc, acc[t][1] * sc);
        *(uint32_t*)(dst + (r0 + 8) * HDIM + col) = h2u(acc[t][2] * sc, acc[t][3] * sc);
    }
}

// ---------------------------------------------------------------------------
// Kernel 2: flash, BQ=64, 128 threads, 3 CTAs/SM. Single-pass fp16 S and PV.
// smem: Q16 + K16 + V16 = 3 x 17408 = 52224 B.
// ---------------------------------------------------------------------------
#define F_STR  272
#define F_TILE 17408u
#define SM_Q   0u
#define SM_K   F_TILE
#define SM_V   (2u * F_TILE)
#define F_SM_TOT (3 * F_TILE)    // 52224

__device__ __forceinline__ void k_issue(uint32_t smb, int b, int t0, int tid) {
    const __half* src = K16_g + ((size_t)b * TLEN + t0) * HDIM;
#pragma unroll
    for (int i = 0; i < 8; i++) {
        int u = tid + i * 128, r = u >> 4, c = u & 15;
        CPA(smb + SM_K + r * F_STR + c * 16, src + r * HDIM + c * 8);
    }
    CPC();
}
__device__ __forceinline__ void v_issue(uint32_t smb, int b, int t0, int tid) {
    const __half* src = V16_g + ((size_t)b * TLEN + t0) * HDIM;
#pragma unroll
    for (int i = 0; i < 8; i++) {
        int u = tid + i * 128, r = u >> 4, c = u & 15;
        CPA(smb + SM_V + r * F_STR + c * 16, src + r * HDIM + c * 8);
    }
    CPC();
}

__global__ void __launch_bounds__(128, 3) flash_mma(float* __restrict__ Out) {
    extern __shared__ char sm[];
    const uint32_t smb = smem_to_u32(sm);
    const int tid = threadIdx.x, w = tid >> 5, l = tid & 31;
    const int qt = 63 - (int)blockIdx.y, b = blockIdx.x;   // LPT: heavy first
    const size_t gq0 = (size_t)b * TLEN + (size_t)qt * 64;
    const int nsteps = qt + 1;

    // prologue: Q tile + K(0), one group
    {
        const __half* src = Q16_g + gq0 * HDIM;
#pragma unroll
        for (int i = 0; i < 8; i++) {
            int u = tid + i * 128, r = u >> 4, c = u & 15;
            CPA(smb + SM_Q + r * F_STR + c * 16, src + r * HDIM + c * 8);
        }
    }
    k_issue(smb, b, 0, tid);   // commits Q+K together

    const int sub = l >> 3, l7 = l & 7;
    const uint32_t qoff = smb + SM_Q + (uint32_t)(w * 16 + l7 + (sub & 1) * 8) * F_STR + (l >> 4) * 16;
    const uint32_t koff = smb + SM_K + (uint32_t)((sub >> 1) * 8 + l7) * F_STR + (sub & 1) * 16;
    const uint32_t voff = smb + SM_V + (uint32_t)((sub & 1) * 8 + l7) * F_STR + (l >> 4) * 16;
    const int gl = l >> 2, tq = l & 3;
    const int rg0 = qt * 64 + w * 16 + gl;

    float o[16][4];
#pragma unroll
    for (int i = 0; i < 16; i++) o[i][0] = o[i][1] = o[i][2] = o[i][3] = 0.f;
    float la0 = 0.f, la1 = 0.f;

    for (int kt = 0; kt < nsteps; kt++) {
        const int t0 = kt * 64;
        asm volatile("cp.async.wait_group 0;");   // K(kt) (and Q at kt=0) ready
        __syncthreads();                           // V buffer free, K visible
        v_issue(smb, b, t0, tid);                  // V(kt) arrives during S

        // ---- S = Q K^T : single-pass fp16 ----
        float s[8][4];
#pragma unroll
        for (int i = 0; i < 8; i++) s[i][0] = s[i][1] = s[i][2] = s[i][3] = 0.f;
#pragma unroll
        for (int kc = 0; kc < 8; kc++) {
            uint32_t qf[4];
            LDSM4(qf, qoff + kc * 32);
            uint32_t kh[4][4];
#pragma unroll
            for (int g = 0; g < 4; g++)
                LDSM4(kh[g], koff + g * (16 * F_STR) + kc * 32);
#pragma unroll
            for (int g = 0; g < 4; g++) {
                MMAH(s[2 * g], qf, kh[g]);
                MMAH(s[2 * g + 1], qf, kh[g] + 2);
            }
        }

        asm volatile("cp.async.wait_group 0;");   // V(kt) arrived
        __syncthreads();                           // S K-reads done + V visible
        if (kt + 1 < nsteps)
            k_issue(smb, b, t0 + 64, tid);         // K(kt+1) arrives during PV

        // ---- softmax (fp16 P) + PV single-pass fp16 ----
        const bool msk = (kt == qt);
#pragma unroll
        for (int kc2 = 0; kc2 < 4; kc2++) {
            uint32_t pc[4];
#pragma unroll
            for (int h = 0; h < 2; h++) {
                const int nt = 2 * kc2 + h;
                int col = t0 + nt * 8 + tq * 2;
                float e0 = fexp(s[nt][0]), e1 = fexp(s[nt][1]);
                float e2 = fexp(s[nt][2]), e3 = fexp(s[nt][3]);
                if (msk) {
                    if (col > rg0) e0 = 0.f;
                    if (col + 1 > rg0) e1 = 0.f;
                    if (col > rg0 + 8) e2 = 0.f;
                    if (col + 1 > rg0 + 8) e3 = 0.f;
                }
                la0 += e0 + e1;
                la1 += e2 + e3;
                pc[h * 2 + 0] = h2u(e0, e1);
                pc[h * 2 + 1] = h2u(e2, e3);
            }
#pragma unroll
            for (int ng = 0; ng < 2; ng++) {
                uint32_t vf[4][4];
#pragma unroll
                for (int j = 0; j < 4; j++)
                    LDSM4T(vf[j], voff + kc2 * (16 * F_STR) + (ng * 4 + j) * 32);
#pragma unroll
                for (int j = 0; j < 4; j++) {
                    MMAH(o[2 * (ng * 4 + j)], pc, vf[j]);
                    MMAH(o[2 * (ng * 4 + j) + 1], pc, vf[j] + 2);
                }
            }
        }
    }

    la0 += __shfl_xor_sync(0xffffffffu, la0, 1);
    la0 += __shfl_xor_sync(0xffffffffu, la0, 2);
    la1 += __shfl_xor_sync(0xffffffffu, la1, 1);
    la1 += __shfl_xor_sync(0xffffffffu, la1, 2);
    const float rl0 = 1.f / la0, rl1 = 1.f / la1;
    float* o0 = Out + (gq0 + w * 16 + gl) * HDIM + tq * 2;
    float* o1 = o0 + 8 * HDIM;
#pragma unroll
    for (int nt2 = 0; nt2 < 16; nt2++) {
        *(float2*)(o0 + nt2 * 8) = make_float2(o[nt2][0] * rl0, o[nt2][1] * rl0);
        *(float2*)(o1 + nt2 * 8) = make_float2(o[nt2][2] * rl1, o[nt2][3] * rl1);
    }
}

// ---------------------------------------------------------------------------
extern "C" void kernel_launch(void* const* d_in, const int* in_sizes, int n_in,
                              void* d_out, int out_size) {
    const float* x  = (const float*)d_in[0];
    const float* Wq = (const float*)d_in[1];
    const float* Wk = (const float*)d_in[2];
    const float* Wv = (const float*)d_in[3];
    float* out = (float*)d_out;
    (void)in_sizes; (void)n_in; (void)out_size;

    split_w<<<96, 512>>>(Wq, Wk, Wv);

    cudaFuncSetAttribute(proj_mma, cudaFuncAttributeMaxDynamicSharedMemorySize, PSM_TOT);
    proj_mma<<<dim3(512, 3), 128, PSM_TOT>>>(x);

    cudaFuncSetAttribute(flash_mma, cudaFuncAttributeMaxDynamicSharedMemorySize, F_SM_TOT);
    flash_mma<<<dim3(BSZ, 64), 128, F_SM_TOT>>>(out);
}

// round 17
// speedup vs baseline: 1.6166x; 1.4404x over previous
#include <cuda_runtime.h>
#include <cuda_bf16.h>
#include <cuda_fp16.h>
#include <stdint.h>

#define BSZ   8
#define TLEN  4096
#define EDIM  1024
#define HDIM  128
#define MTOT  (BSZ * TLEN)

// Q,K,V: single fp16 row-major [t][h] (Q pre-scaled by 1/sqrt(H)).
__device__ __half Q16_g[MTOT * HDIM];
__device__ __half K16_g[MTOT * HDIM];
__device__ __half V16_g[MTOT * HDIM];
// fp16 weights [which][k][n]
__device__ __half W16_g[3 * EDIM * HDIM];

// ---------------- helpers ----------------
__device__ __forceinline__ uint32_t smem_to_u32(const void* p) {
    uint32_t a;
    asm("{ .reg .u64 t; cvta.to.shared.u64 t, %1; cvt.u32.u64 %0, t; }" : "=r"(a) : "l"(p));
    return a;
}
#define LDSM4(R, A) asm volatile( \
    "ldmatrix.sync.aligned.m8n8.x4.shared.b16 {%0,%1,%2,%3}, [%4];" \
    : "=r"((R)[0]), "=r"((R)[1]), "=r"((R)[2]), "=r"((R)[3]) : "r"(A))
#define LDSM4T(R, A) asm volatile( \
    "ldmatrix.sync.aligned.m8n8.x4.trans.shared.b16 {%0,%1,%2,%3}, [%4];" \
    : "=r"((R)[0]), "=r"((R)[1]), "=r"((R)[2]), "=r"((R)[3]) : "r"(A))
#define MMAH(C, A, B) asm volatile( \
    "mma.sync.aligned.m16n8k16.row.col.f32.f16.f16.f32 " \
    "{%0,%1,%2,%3},{%4,%5,%6,%7},{%8,%9},{%0,%1,%2,%3};" \
    : "+f"((C)[0]), "+f"((C)[1]), "+f"((C)[2]), "+f"((C)[3]) \
    : "r"((A)[0]), "r"((A)[1]), "r"((A)[2]), "r"((A)[3]), "r"((B)[0]), "r"((B)[1]))
#define CPA(S, G) asm volatile("cp.async.cg.shared.global [%0], [%1], 16;" \
    :: "r"(S), "l"(G))
#define CPC() asm volatile("cp.async.commit_group;")

__device__ __forceinline__ float fexp(float x) {      // FMA-pipe exp, ~2e-6 rel
    float t = x * 1.4426950408889634f;
    float k = rintf(t);
    float u = (t - k) * 0.6931471805599453f;
    float p = 1.f + u * (1.f + u * (0.5f + u * (0.16666667f +
              u * (0.041666667f + u * 0.0083333333f))));
    return p * __int_as_float(((int)k + 127) << 23);
}
__device__ __forceinline__ uint32_t h2u(float a, float b) {
    __half2 t = __floats2half2_rn(a, b);
    return *(uint32_t*)&t;
}

// ---------------------------------------------------------------------------
// Kernel 0: convert W to fp16.
// ---------------------------------------------------------------------------
__global__ __launch_bounds__(512) void conv_w(const float* __restrict__ Wq,
                                              const float* __restrict__ Wk,
                                              const float* __restrict__ Wv) {
    int t = blockIdx.x * 512 + threadIdx.x;
    int base = t * 8;
    int which = base >> 17;
    const float* s = ((which == 0) ? Wq : (which == 1) ? Wk : Wv) + (base & 131071);
    float4 a = *(const float4*)s, b = *(const float4*)(s + 4);
    *(uint4*)(W16_g + base) =
        make_uint4(h2u(a.x, a.y), h2u(a.z, a.w), h2u(b.x, b.y), h2u(b.z, b.w));
}

// ---------------------------------------------------------------------------
// Kernel 1: projection, single-pass fp16. BM=64, 128 threads, 3 CTAs/SM.
// A and B double-buffered -> ONE barrier per k-step.
// smem: 2 x A(64x144B) + 2 x B(64x272B) = 53248 B.
// ---------------------------------------------------------------------------
#define PA_STR 144
#define PB_STR 272
#define PA_TILE (64 * PA_STR)            // 9216
#define PB_TILE (64 * PB_STR)            // 17408
#define PSM_TOT (2 * PA_TILE + 2 * PB_TILE)   // 53248

__global__ __launch_bounds__(128, 3) void proj_mma(const float* __restrict__ X) {
    extern __shared__ char psm[];
    const int which = blockIdx.y;
    const int m0 = blockIdx.x * 64, tid = threadIdx.x;
    const int w = tid >> 5, l = tid & 31;
    const int sub = l >> 3, l7 = l & 7;
    const uint32_t smb = smem_to_u32(psm);
    const uint32_t B_base = smb + 2 * PA_TILE;

    const uint32_t aoff = (uint32_t)(w * 16 + l7 + (sub & 1) * 8) * PA_STR + (l >> 4) * 16;
    const uint32_t boff = (uint32_t)((sub & 1) * 8 + l7) * PB_STR + (l >> 4) * 16;

    const __half* w16 = W16_g + which * 131072;

    float acc[16][4];
#pragma unroll
    for (int i = 0; i < 16; i++) acc[i][0] = acc[i][1] = acc[i][2] = acc[i][3] = 0.f;
    float4 xa[8];

    // prologue: x(0) regs + B(0) cp.async into buf 0
#pragma unroll
    for (int i = 0; i < 8; i++) {
        int idx = tid + i * 128, r = idx >> 4, c4 = idx & 15;
        xa[i] = *(const float4*)(X + (size_t)(m0 + r) * EDIM + c4 * 4);
    }
#pragma unroll
    for (int i = 0; i < 8; i++) {
        int u = tid + i * 128, r = u >> 4, c = u & 15;
        CPA(B_base + r * PB_STR + c * 16, w16 + r * HDIM + c * 8);
    }
    CPC();

    for (int s = 0; s < 16; s++) {
        const uint32_t Abuf = smb + (uint32_t)(s & 1) * PA_TILE;
        const uint32_t Bbuf = B_base + (uint32_t)(s & 1) * PB_TILE;

        // store A(s) fp16 into its buffer (other buffer than MMA(s-1) read)
        char* Ap = psm + (s & 1) * PA_TILE;
#pragma unroll
        for (int i = 0; i < 8; i++) {
            int idx = tid + i * 128, r = idx >> 4, c4 = idx & 15;
            *(uint2*)(Ap + r * PA_STR + c4 * 8) =
                make_uint2(h2u(xa[i].x, xa[i].y), h2u(xa[i].z, xa[i].w));
        }
        asm volatile("cp.async.wait_group 0;");   // B(s) arrived
        __syncthreads();                           // A(s)+B(s) visible; old bufs free

        if (s < 15) {
            int k0n = (s + 1) * 64;
#pragma unroll
            for (int i = 0; i < 8; i++) {
                int idx = tid + i * 128, r = idx >> 4, c4 = idx & 15;
                xa[i] = *(const float4*)(X + (size_t)(m0 + r) * EDIM + k0n + c4 * 4);
            }
            const __half* wn = w16 + (size_t)(s + 1) * 64 * HDIM;
            const uint32_t Bn = B_base + (uint32_t)((s + 1) & 1) * PB_TILE;
#pragma unroll
            for (int i = 0; i < 8; i++) {
                int u = tid + i * 128, r = u >> 4, c = u & 15;
                CPA(Bn + r * PB_STR + c * 16, wn + r * HDIM + c * 8);
            }
            CPC();
        }

        // single-pass fp16 MMA
#pragma unroll
        for (int kc = 0; kc < 4; kc++) {
            uint32_t af[4];
            LDSM4(af, Abuf + aoff + kc * 32);
#pragma unroll
            for (int ng = 0; ng < 8; ng++) {
                uint32_t bf[4];
                LDSM4T(bf, Bbuf + boff + kc * (16 * PB_STR) + ng * 32);
                MMAH(acc[2 * ng], af, bf);
                MMAH(acc[2 * ng + 1], af, bf + 2);
            }
        }
        // no trailing barrier: next step's single barrier protects reuse
    }

    // epilogue: fp16 store (Q scaled by 1/sqrt(H))
    const float sc = (which == 0) ? 0.08838834764831845f : 1.f;
    __half* dst = (which == 0) ? Q16_g : (which == 1) ? K16_g : V16_g;
    const int gl = l >> 2, tq = l & 3;
    const size_t r0 = (size_t)m0 + w * 16 + gl;
#pragma unroll
    for (int t = 0; t < 16; t++) {
        int col = t * 8 + tq * 2;
        *(uint32_t*)(dst + r0 * HDIM + col)       = h2u(acc[t][0] * sc, acc[t][1] * sc);
        *(uint32_t*)(dst + (r0 + 8) * HDIM + col) = h2u(acc[t][2] * sc, acc[t][3] * sc);
    }
}

// ---------------------------------------------------------------------------
// Kernel 2: flash, BQ=64, 128 threads, 3 CTAs/SM. Single-pass fp16. (R16 win.)
// ---------------------------------------------------------------------------
#define F_STR  272
#define F_TILE 17408u
#define SM_Q   0u
#define SM_K   F_TILE
#define SM_V   (2u * F_TILE)
#define F_SM_TOT (3 * F_TILE)    // 52224

__device__ __forceinline__ void k_issue(uint32_t smb, int b, int t0, int tid) {
    const __half* src = K16_g + ((size_t)b * TLEN + t0) * HDIM;
#pragma unroll
    for (int i = 0; i < 8; i++) {
        int u = tid + i * 128, r = u >> 4, c = u & 15;
        CPA(smb + SM_K + r * F_STR + c * 16, src + r * HDIM + c * 8);
    }
    CPC();
}
__device__ __forceinline__ void v_issue(uint32_t smb, int b, int t0, int tid) {
    const __half* src = V16_g + ((size_t)b * TLEN + t0) * HDIM;
#pragma unroll
    for (int i = 0; i < 8; i++) {
        int u = tid + i * 128, r = u >> 4, c = u & 15;
        CPA(smb + SM_V + r * F_STR + c * 16, src + r * HDIM + c * 8);
    }
    CPC();
}

__global__ void __launch_bounds__(128, 3) flash_mma(float* __restrict__ Out) {
    extern __shared__ char sm[];
    const uint32_t smb = smem_to_u32(sm);
    const int tid = threadIdx.x, w = tid >> 5, l = tid & 31;
    const int qt = 63 - (int)blockIdx.y, b = blockIdx.x;   // LPT: heavy first
    const size_t gq0 = (size_t)b * TLEN + (size_t)qt * 64;
    const int nsteps = qt + 1;

    // prologue: Q tile + K(0), one group
    {
        const __half* src = Q16_g + gq0 * HDIM;
#pragma unroll
        for (int i = 0; i < 8; i++) {
            int u = tid + i * 128, r = u >> 4, c = u & 15;
            CPA(smb + SM_Q + r * F_STR + c * 16, src + r * HDIM + c * 8);
        }
    }
    k_issue(smb, b, 0, tid);   // commits Q+K together

    const int sub = l >> 3, l7 = l & 7;
    const uint32_t qoff = smb + SM_Q + (uint32_t)(w * 16 + l7 + (sub & 1) * 8) * F_STR + (l >> 4) * 16;
    const uint32_t koff = smb + SM_K + (uint32_t)((sub >> 1) * 8 + l7) * F_STR + (sub & 1) * 16;
    const uint32_t voff = smb + SM_V + (uint32_t)((sub & 1) * 8 + l7) * F_STR + (l >> 4) * 16;
    const int gl = l >> 2, tq = l & 3;
    const int rg0 = qt * 64 + w * 16 + gl;

    float o[16][4];
#pragma unroll
    for (int i = 0; i < 16; i++) o[i][0] = o[i][1] = o[i][2] = o[i][3] = 0.f;
    float la0 = 0.f, la1 = 0.f;

    for (int kt = 0; kt < nsteps; kt++) {
        const int t0 = kt * 64;
        asm volatile("cp.async.wait_group 0;");   // K(kt) (and Q at kt=0) ready
        __syncthreads();                           // V buffer free, K visible
        v_issue(smb, b, t0, tid);                  // V(kt) arrives during S

        // ---- S = Q K^T : single-pass fp16 ----
        float s[8][4];
#pragma unroll
        for (int i = 0; i < 8; i++) s[i][0] = s[i][1] = s[i][2] = s[i][3] = 0.f;
#pragma unroll
        for (int kc = 0; kc < 8; kc++) {
            uint32_t qf[4];
            LDSM4(qf, qoff + kc * 32);
            uint32_t kh[4][4];
#pragma unroll
            for (int g = 0; g < 4; g++)
                LDSM4(kh[g], koff + g * (16 * F_STR) + kc * 32);
#pragma unroll
            for (int g = 0; g < 4; g++) {
                MMAH(s[2 * g], qf, kh[g]);
                MMAH(s[2 * g + 1], qf, kh[g] + 2);
            }
        }

        asm volatile("cp.async.wait_group 0;");   // V(kt) arrived
        __syncthreads();                           // S K-reads done + V visible
        if (kt + 1 < nsteps)
            k_issue(smb, b, t0 + 64, tid);         // K(kt+1) arrives during PV

        // ---- softmax (fp16 P) + PV single-pass fp16 ----
        const bool msk = (kt == qt);
#pragma unroll
        for (int kc2 = 0; kc2 < 4; kc2++) {
            uint32_t pc[4];
#pragma unroll
            for (int h = 0; h < 2; h++) {
                const int nt = 2 * kc2 + h;
                int col = t0 + nt * 8 + tq * 2;
                float e0 = fexp(s[nt][0]), e1 = fexp(s[nt][1]);
                float e2 = fexp(s[nt][2]), e3 = fexp(s[nt][3]);
                if (msk) {
                    if (col > rg0) e0 = 0.f;
                    if (col + 1 > rg0) e1 = 0.f;
                    if (col > rg0 + 8) e2 = 0.f;
                    if (col + 1 > rg0 + 8) e3 = 0.f;
                }
                la0 += e0 + e1;
                la1 += e2 + e3;
                pc[h * 2 + 0] = h2u(e0, e1);
                pc[h * 2 + 1] = h2u(e2, e3);
            }
#pragma unroll
            for (int ng = 0; ng < 2; ng++) {
                uint32_t vf[4][4];
#pragma unroll
                for (int j = 0; j < 4; j++)
                    LDSM4T(vf[j], voff + kc2 * (16 * F_STR) + (ng * 4 + j) * 32);
#pragma unroll
                for (int j = 0; j < 4; j++) {
                    MMAH(o[2 * (ng * 4 + j)], pc, vf[j]);
                    MMAH(o[2 * (ng * 4 + j) + 1], pc, vf[j] + 2);
                }
            }
        }
    }

    la0 += __shfl_xor_sync(0xffffffffu, la0, 1);
    la0 += __shfl_xor_sync(0xffffffffu, la0, 2);
    la1 += __shfl_xor_sync(0xffffffffu, la1, 1);
    la1 += __shfl_xor_sync(0xffffffffu, la1, 2);
    const float rl0 = 1.f / la0, rl1 = 1.f / la1;
    float* o0 = Out + (gq0 + w * 16 + gl) * HDIM + tq * 2;
    float* o1 = o0 + 8 * HDIM;
#pragma unroll
    for (int nt2 = 0; nt2 < 16; nt2++) {
        *(float2*)(o0 + nt2 * 8) = make_float2(o[nt2][0] * rl0, o[nt2][1] * rl0);
        *(float2*)(o1 + nt2 * 8) = make_float2(o[nt2][2] * rl1, o[nt2][3] * rl1);
    }
}

// ---------------------------------------------------------------------------
extern "C" void kernel_launch(void* const* d_in, const int* in_sizes, int n_in,
                              void* d_out, int out_size) {
    const float* x  = (const float*)d_in[0];
    const float* Wq = (const float*)d_in[1];
    const float* Wk = (const float*)d_in[2];
    const float* Wv = (const float*)d_in[3];
    float* out = (float*)d_out;
    (void)in_sizes; (void)n_in; (void)out_size;

    conv_w<<<96, 512>>>(Wq, Wk, Wv);

    cudaFuncSetAttribute(proj_mma, cudaFuncAttributeMaxDynamicSharedMemorySize, PSM_TOT);
    proj_mma<<<dim3(512, 3), 128, PSM_TOT>>>(x);

    cudaFuncSetAttribute(flash_mma, cudaFuncAttributeMaxDynamicSharedMemorySize, F_SM_TOT);
    flash_mma<<<dim3(BSZ, 64), 128, F_SM_TOT>>>(out);
}